// round 7
// baseline (speedup 1.0000x reference)
#include <cuda_runtime.h>

#define NB    8192     // B*N total rows
#define NPTS  4096     // nodes per batch
#define FDIM  64
#define KSEL  21       // k+1 (drop the smallest afterwards)
#define TPB   256      // 8 warps = 8 queries per block

// ---------------- scratch (device globals; no allocation allowed) ----------
__device__ float4 g_pos4[NB];          // (x,y,z,sq)
__device__ float  g_Wh[NB * FDIM];
__device__ float  g_f1[NB];
__device__ float  g_f2[NB];
__device__ float  g_base[NB * FDIM];   // relu(pos@Wp + bp)

__device__ __forceinline__ unsigned int fkey(float f) {
    unsigned int u = __float_as_uint(f);
    return u ^ (0x80000000u | (unsigned int)((int)u >> 31));
}
__device__ __forceinline__ unsigned long long ullmin2(unsigned long long a,
                                                      unsigned long long b) {
    return a < b ? a : b;
}

// ---------------- kernel A: per-node prep ----------------------------------
__global__ void prep_kernel(const float* __restrict__ x,
                            const float* __restrict__ pos,
                            const float* __restrict__ W,
                            const float* __restrict__ a,
                            const float* __restrict__ Wp,
                            const float* __restrict__ bp) {
    int row = blockIdx.x;
    int j   = threadIdx.x;
    __shared__ float xs[FDIM];
    __shared__ float red[4];

    xs[j] = x[row * FDIM + j];
    __syncthreads();

    float acc = 0.f;
#pragma unroll 16
    for (int i = 0; i < FDIM; i++)
        acc += xs[i] * W[i * FDIM + j];
    g_Wh[row * FDIM + j] = acc;

    float p1 = acc * a[j];
    float p2 = acc * a[FDIM + j];
#pragma unroll
    for (int off = 16; off; off >>= 1) {
        p1 += __shfl_down_sync(0xffffffffu, p1, off);
        p2 += __shfl_down_sync(0xffffffffu, p2, off);
    }
    int lane = j & 31, wid = j >> 5;
    if (lane == 0) { red[wid] = p1; red[2 + wid] = p2; }

    float px = pos[row * 3 + 0];
    float py = pos[row * 3 + 1];
    float pz = pos[row * 3 + 2];
    float bj = px * Wp[j] + py * Wp[FDIM + j] + pz * Wp[2 * FDIM + j] + bp[j];
    g_base[row * FDIM + j] = bj > 0.f ? bj : 0.f;

    __syncthreads();
    if (j == 0) {
        g_f1[row] = red[0] + red[1];
        g_f2[row] = red[2] + red[3];
        float sq  = px * px + py * py + pz * pz;
        g_pos4[row] = make_float4(px, py, pz, sq);
    }
}

// branchless stable float-key insert level; equal keys keep the earlier
// (smaller-idx) element above -> stable like jax top_k.
#define INS_LEVF(kk, ii, ck, ci)                          \
    {                                                     \
        bool c = ck < kk;                                 \
        float nk = c ? ck : kk;                           \
        unsigned int ni = c ? ci : ii;                    \
        ck = c ? kk : ck;  ci = c ? ii : ci;              \
        kk = nk;  ii = ni;                                \
    }

#define CE64(lo, hi)                                      \
    {                                                     \
        unsigned long long mn = lo < hi ? lo : hi;        \
        hi = lo < hi ? hi : lo;                           \
        lo = mn;                                          \
    }

// ---------------- kernel B: warp-per-query kNN(21) + attention -------------
// One warp per query. Lane l owns candidates m = l + 32*i, i = 0..127, as
// two cascade streams (i<64 / i>=64). No shared memory, no block barriers.
__global__ void __launch_bounds__(TPB)
knn_attn_kernel(float* __restrict__ out) {
    const unsigned FULL = 0xffffffffu;
    int lane = threadIdx.x & 31;
    int wid  = threadIdx.x >> 5;
    int row  = blockIdx.x * (TPB / 32) + wid;      // this warp's query
    int browbase = (row >> 12) << 12;              // first row of batch
    const float4* pb = g_pos4 + browbase;

    float4 q = g_pos4[row];

    // ---- phase 1: two independent branchless top-4 cascades (float keys) --
    const float INF = __int_as_float(0x7f800000);
    float ak0 = INF, ak1 = INF, ak2 = INF, ak3 = INF;
    float bk0 = INF, bk1 = INF, bk2 = INF, bk3 = INF;
    unsigned int ai0 = 0xFFFu, ai1 = 0xFFFu, ai2 = 0xFFFu, ai3 = 0xFFFu;
    unsigned int bi0 = 0xFFFu, bi1 = 0xFFFu, bi2 = 0xFFFu, bi3 = 0xFFFu;
#pragma unroll 4
    for (int i = 0; i < 64; i++) {
        int mA = lane + 32 * i;
        int mB = lane + 32 * (i + 64);
        float4 pA = pb[mA];
        float4 pB = pb[mB];

        float dotA = fmaf(q.z, pA.z, fmaf(q.y, pA.y, q.x * pA.x));
        float ck   = fmaf(-2.f, dotA, q.w + pA.w);
        unsigned int ci = (unsigned int)mA;
        INS_LEVF(ak0, ai0, ck, ci)
        INS_LEVF(ak1, ai1, ck, ci)
        INS_LEVF(ak2, ai2, ck, ci)
        INS_LEVF(ak3, ai3, ck, ci)

        float dotB = fmaf(q.z, pB.z, fmaf(q.y, pB.y, q.x * pB.x));
        float dk   = fmaf(-2.f, dotB, q.w + pB.w);
        unsigned int di = (unsigned int)mB;
        INS_LEVF(bk0, bi0, dk, di)
        INS_LEVF(bk1, bi1, dk, di)
        INS_LEVF(bk2, bi2, dk, di)
        INS_LEVF(bk3, bi3, dk, di)
    }

    // ---- union-merge the two sorted 4-lists -> sorted top-4 + bound -------
    unsigned long long l1, l2, l3;       // list tail (head kept unpacked)
    unsigned int hk, hidx, hflag;
    {
        unsigned long long pa0 = (((unsigned long long)fkey(ak0)) << 13) | ai0;
        unsigned long long pa1 = (((unsigned long long)fkey(ak1)) << 13) | ai1;
        unsigned long long pa2 = (((unsigned long long)fkey(ak2)) << 13) | ai2;
        unsigned long long pa3 = (((unsigned long long)fkey(ak3)) << 13) | ai3;
        unsigned long long pb0 = (((unsigned long long)fkey(bk0)) << 13) | bi0;
        unsigned long long pb1 = (((unsigned long long)fkey(bk1)) << 13) | bi1;
        unsigned long long pb2 = (((unsigned long long)fkey(bk2)) << 13) | bi2;
        unsigned long long pb3 = (((unsigned long long)fkey(bk3)) << 13) | bi3;
        unsigned long long c0 = ullmin2(pa0, pb3);
        unsigned long long c1 = ullmin2(pa1, pb2);
        unsigned long long c2 = ullmin2(pa2, pb1);
        unsigned long long c3 = ullmin2(pa3, pb0);
        CE64(c0, c2) CE64(c1, c3) CE64(c0, c1) CE64(c2, c3)
        hk    = (unsigned int)(c0 >> 13);
        hidx  = (unsigned int)c0 & 0xFFFu;
        hflag = 0;                        // c0 is never the bound
        l1 = c1; l2 = c2; l3 = c3 | 0x1000ull;   // flag the 4th (bound)
    }

    // ---- 21 REDUX.MIN merge rounds, all in-warp ---------------------------
    unsigned int nbr = 0;                 // lane r-1 keeps neighbor r-1
    bool hitBound = false;
    int hp = 1;
#pragma unroll 1
    for (int r = 0; r < KSEL; r++) {
        unsigned int w = __reduce_min_sync(FULL, hk);
        unsigned int cand = (hk == w) ? hidx : 0xFFFFu;
        unsigned int m = __reduce_min_sync(FULL, cand);
        if (lane == r - 1) nbr = m;       // r>=1 rounds record neighbors
        bool mine = (hk == w) && (hidx == m);
        if (mine) {
            hitBound |= (hflag != 0);
            unsigned long long v = (hp == 1) ? l1 : (hp == 2) ? l2
                                 : (hp == 3) ? l3 : ~0ull;
            hp++;
            hk    = (unsigned int)(v >> 13);
            hidx  = (unsigned int)v & 0xFFFu;
            hflag = (unsigned int)(v >> 12) & 1u;
        }
    }

    // ---- exact fallback (rare): in-warp extract-min with removal bitmap ---
    if (__any_sync(FULL, hitBound)) {
        unsigned long long rm0 = 0ull, rm1 = 0ull;   // bits i=0..63 / 64..127
        unsigned long long v = ~0ull;
#pragma unroll 1
        for (int i = 0; i < 128; i++) {
            int m = lane + 32 * i;
            float4 p = pb[m];
            float dot = fmaf(q.z, p.z, fmaf(q.y, p.y, q.x * p.x));
            float d2  = fmaf(-2.f, dot, q.w + p.w);
            unsigned long long k64 =
                (((unsigned long long)fkey(d2)) << 13) | (unsigned int)m;
            v = ullmin2(v, k64);
        }
        for (int r = 0; r < KSEL; r++) {
            unsigned long long vv = v;
#pragma unroll
            for (int off = 16; off; off >>= 1)
                vv = ullmin2(vv, __shfl_xor_sync(FULL, vv, off));
            unsigned int m = (unsigned int)vv & 0xFFFu;
            if (lane == r - 1) nbr = m;
            if (lane == (int)(m & 31u)) {           // owner removes + rescans
                int i = (int)(m >> 5);
                if (i < 64) rm0 |= 1ull << i; else rm1 |= 1ull << (i - 64);
                unsigned long long nv = ~0ull;
#pragma unroll 1
                for (int ii = 0; ii < 128; ii++) {
                    bool rem = (ii < 64) ? ((rm0 >> ii) & 1ull)
                                         : ((rm1 >> (ii - 64)) & 1ull);
                    if (rem) continue;
                    int mm = lane + 32 * ii;
                    float4 p = pb[mm];
                    float dot = fmaf(q.z, p.z, fmaf(q.y, p.y, q.x * p.x));
                    float d2  = fmaf(-2.f, dot, q.w + p.w);
                    unsigned long long k64 =
                        (((unsigned long long)fkey(d2)) << 13) |
                        (unsigned int)mm;
                    nv = ullmin2(nv, k64);
                }
                v = nv;
            }
        }
    }

    // ---- softmax over the 20 neighbors (in-warp, lanes 0..19 hold them) ---
    float e = -1e30f;
    if (lane < KSEL - 1) {
        float val = g_f1[row] + g_f2[browbase + (int)nbr];
        e = val > 0.f ? val : 0.2f * val;            // leaky relu 0.2
    }
    float mx = e;
#pragma unroll
    for (int off = 16; off; off >>= 1)
        mx = fmaxf(mx, __shfl_xor_sync(FULL, mx, off));
    float ex = (lane < KSEL - 1) ? expf(e - mx) : 0.f;
    float sm = ex;
#pragma unroll
    for (int off = 16; off; off >>= 1)
        sm += __shfl_xor_sync(FULL, sm, off);
    float attn = ex / sm;                            // valid on lanes < 20

    // ---- weighted Wh gather + base + elu (2 features per lane) ------------
    float acc0 = g_base[row * FDIM + lane];
    float acc1 = g_base[row * FDIM + 32 + lane];
#pragma unroll
    for (int j = 0; j < KSEL - 1; j++) {
        int   mj = (int)__shfl_sync(FULL, nbr, j);
        float aj = __shfl_sync(FULL, attn, j);
        const float* wr = g_Wh + (browbase + mj) * FDIM;
        acc0 = fmaf(aj, wr[lane],      acc0);
        acc1 = fmaf(aj, wr[32 + lane], acc1);
    }
    out[row * FDIM + lane]      = acc0 > 0.f ? acc0 : expm1f(acc0);
    out[row * FDIM + 32 + lane] = acc1 > 0.f ? acc1 : expm1f(acc1);
}

// ---------------- launch ----------------------------------------------------
extern "C" void kernel_launch(void* const* d_in, const int* in_sizes, int n_in,
                              void* d_out, int out_size) {
    (void)in_sizes; (void)n_in; (void)out_size;
    const float* x   = (const float*)d_in[0];
    const float* pos = (const float*)d_in[1];
    const float* W   = (const float*)d_in[2];
    const float* a   = (const float*)d_in[3];
    const float* Wp  = (const float*)d_in[4];
    const float* bp  = (const float*)d_in[5];
    float* out = (float*)d_out;

    prep_kernel<<<NB, FDIM>>>(x, pos, W, a, Wp, bp);
    knn_attn_kernel<<<NB / (TPB / 32), TPB>>>(out);
}

// round 8
// speedup vs baseline: 5.1580x; 5.1580x over previous
#include <cuda_runtime.h>

#define NB    8192     // B*N total rows
#define NPTS  4096     // nodes per batch
#define FDIM  64
#define KSEL  21       // k+1 (drop the smallest afterwards)
#define TPB   256      // 8 warps = 8 queries per block

// ---------------- scratch (device globals; no allocation allowed) ----------
__device__ float4 g_pos4[NB];          // (x,y,z,sq)
__device__ float  g_Wh[NB * FDIM];
__device__ float  g_f1[NB];
__device__ float  g_f2[NB];
__device__ float  g_base[NB * FDIM];   // relu(pos@Wp + bp)

__device__ __forceinline__ unsigned int fkey(float f) {
    unsigned int u = __float_as_uint(f);
    return u ^ (0x80000000u | (unsigned int)((int)u >> 31));
}
__device__ __forceinline__ unsigned long long ullmin2(unsigned long long a,
                                                      unsigned long long b) {
    return a < b ? a : b;
}

// ---------------- kernel A: per-node prep ----------------------------------
__global__ void prep_kernel(const float* __restrict__ x,
                            const float* __restrict__ pos,
                            const float* __restrict__ W,
                            const float* __restrict__ a,
                            const float* __restrict__ Wp,
                            const float* __restrict__ bp) {
    int row = blockIdx.x;
    int j   = threadIdx.x;
    __shared__ float xs[FDIM];
    __shared__ float red[4];

    xs[j] = x[row * FDIM + j];
    __syncthreads();

    float acc = 0.f;
#pragma unroll 16
    for (int i = 0; i < FDIM; i++)
        acc += xs[i] * W[i * FDIM + j];
    g_Wh[row * FDIM + j] = acc;

    float p1 = acc * a[j];
    float p2 = acc * a[FDIM + j];
#pragma unroll
    for (int off = 16; off; off >>= 1) {
        p1 += __shfl_down_sync(0xffffffffu, p1, off);
        p2 += __shfl_down_sync(0xffffffffu, p2, off);
    }
    int lane = j & 31, wid = j >> 5;
    if (lane == 0) { red[wid] = p1; red[2 + wid] = p2; }

    float px = pos[row * 3 + 0];
    float py = pos[row * 3 + 1];
    float pz = pos[row * 3 + 2];
    float bj = px * Wp[j] + py * Wp[FDIM + j] + pz * Wp[2 * FDIM + j] + bp[j];
    g_base[row * FDIM + j] = bj > 0.f ? bj : 0.f;

    __syncthreads();
    if (j == 0) {
        g_f1[row] = red[0] + red[1];
        g_f2[row] = red[2] + red[3];
        float sq  = px * px + py * py + pz * pz;
        g_pos4[row] = make_float4(px, py, pz, sq);
    }
}

// branchless stable float-key insert level
#define INS_LEVF(kk, ii, ck, ci)                          \
    {                                                     \
        bool c = ck < kk;                                 \
        float nk = c ? ck : kk;                           \
        unsigned int ni = c ? ci : ii;                    \
        ck = c ? kk : ck;  ci = c ? ii : ci;              \
        kk = nk;  ii = ni;                                \
    }
// branchless stable u32-key insert level (refill rescan)
#define INS_LEVU(kk, ii, ck, ci)                          \
    {                                                     \
        bool c = ck < kk;                                 \
        unsigned int nk = c ? ck : kk, ni = c ? ci : ii;  \
        ck = c ? kk : ck;  ci = c ? ii : ci;              \
        kk = nk;  ii = ni;                                \
    }
#define CE64(lo, hi)                                      \
    {                                                     \
        unsigned long long mn = lo < hi ? lo : hi;        \
        hi = lo < hi ? hi : lo;                           \
        lo = mn;                                          \
    }

// ---------------- kernel B: warp-per-query kNN(21) + attention -------------
__global__ void __launch_bounds__(TPB)
knn_attn_kernel(float* __restrict__ out) {
    const unsigned FULL = 0xffffffffu;
    int lane = threadIdx.x & 31;
    int wid  = threadIdx.x >> 5;
    int row  = blockIdx.x * (TPB / 32) + wid;      // this warp's query
    int browbase = (row >> 12) << 12;              // first row of batch
    const float4* pb = g_pos4 + browbase;

    float4 q = g_pos4[row];

    // ---- phase 1: two independent branchless top-4 cascades (float keys) --
    const float INF = __int_as_float(0x7f800000);
    float ak0 = INF, ak1 = INF, ak2 = INF, ak3 = INF;
    float bk0 = INF, bk1 = INF, bk2 = INF, bk3 = INF;
    unsigned int ai0 = 0xFFFu, ai1 = 0xFFFu, ai2 = 0xFFFu, ai3 = 0xFFFu;
    unsigned int bi0 = 0xFFFu, bi1 = 0xFFFu, bi2 = 0xFFFu, bi3 = 0xFFFu;
#pragma unroll 4
    for (int i = 0; i < 64; i++) {
        int mA = lane + 32 * i;
        int mB = lane + 32 * (i + 64);
        float4 pA = pb[mA];
        float4 pB = pb[mB];

        float dotA = fmaf(q.z, pA.z, fmaf(q.y, pA.y, q.x * pA.x));
        float ck   = fmaf(-2.f, dotA, q.w + pA.w);
        unsigned int ci = (unsigned int)mA;
        INS_LEVF(ak0, ai0, ck, ci)
        INS_LEVF(ak1, ai1, ck, ci)
        INS_LEVF(ak2, ai2, ck, ci)
        INS_LEVF(ak3, ai3, ck, ci)

        float dotB = fmaf(q.z, pB.z, fmaf(q.y, pB.y, q.x * pB.x));
        float dk   = fmaf(-2.f, dotB, q.w + pB.w);
        unsigned int di = (unsigned int)mB;
        INS_LEVF(bk0, bi0, dk, di)
        INS_LEVF(bk1, bi1, dk, di)
        INS_LEVF(bk2, bi2, dk, di)
        INS_LEVF(bk3, bi3, dk, di)
    }

    // ---- union-merge into exact sorted top-4 (c0..c3 all exact) -----------
    unsigned long long l1, l2, l3, bound;
    unsigned int hk, hidx, hflag;
    {
        unsigned long long pa0 = (((unsigned long long)fkey(ak0)) << 13) | ai0;
        unsigned long long pa1 = (((unsigned long long)fkey(ak1)) << 13) | ai1;
        unsigned long long pa2 = (((unsigned long long)fkey(ak2)) << 13) | ai2;
        unsigned long long pa3 = (((unsigned long long)fkey(ak3)) << 13) | ai3;
        unsigned long long pb0 = (((unsigned long long)fkey(bk0)) << 13) | bi0;
        unsigned long long pb1 = (((unsigned long long)fkey(bk1)) << 13) | bi1;
        unsigned long long pb2 = (((unsigned long long)fkey(bk2)) << 13) | bi2;
        unsigned long long pb3 = (((unsigned long long)fkey(bk3)) << 13) | bi3;
        unsigned long long c0 = ullmin2(pa0, pb3);
        unsigned long long c1 = ullmin2(pa1, pb2);
        unsigned long long c2 = ullmin2(pa2, pb1);
        unsigned long long c3 = ullmin2(pa3, pb0);
        CE64(c0, c2) CE64(c1, c3) CE64(c0, c1) CE64(c2, c3)
        hk    = (unsigned int)(c0 >> 13);
        hidx  = (unsigned int)c0 & 0xFFFu;
        hflag = 0;
        l1 = c1; l2 = c2; l3 = c3;
        bound = c3 | 0x1000ull;    // sentinel: flagged copy of last exact elem
    }

    // ---- 21 merge rounds; sentinel win -> incremental single-lane refill --
    unsigned int nbr = 0;
    int hp = 1;
    int r  = 0;
    while (r < KSEL) {
        unsigned int w = __reduce_min_sync(FULL, hk);
        unsigned int cand = (hk == w) ? hidx : 0xFFFFu;
        unsigned int m = __reduce_min_sync(FULL, cand);
        bool mine = (hk == w) && (hidx == m);
        if (__ballot_sync(FULL, mine && hflag)) {
            // exhausted lane refills: top-4 of its candidates with packed
            // key strictly greater than the sentinel (== last consumed elem)
            if (mine && hflag) {
                unsigned long long fcut =
                    (((unsigned long long)hk) << 13) | hidx;
                unsigned int k0 = ~0u, k1 = ~0u, k2 = ~0u, k3 = ~0u;
                unsigned int i0 = 0xFFFu, i1 = 0xFFFu, i2 = 0xFFFu,
                             i3 = 0xFFFu;
#pragma unroll 1
                for (int i = 0; i < 128; i++) {
                    int mm = lane + 32 * i;
                    float4 p = pb[mm];
                    float dot = fmaf(q.z, p.z, fmaf(q.y, p.y, q.x * p.x));
                    float d2  = fmaf(-2.f, dot, q.w + p.w);
                    unsigned int key = fkey(d2);
                    unsigned long long pk =
                        (((unsigned long long)key) << 13) | (unsigned int)mm;
                    bool ok = pk > fcut;
                    unsigned int ck = ok ? key : 0xFFFFFFFFu;
                    unsigned int ci = ok ? (unsigned int)mm : 0xFFFu;
                    INS_LEVU(k0, i0, ck, ci)
                    INS_LEVU(k1, i1, ck, ci)
                    INS_LEVU(k2, i2, ck, ci)
                    INS_LEVU(k3, i3, ck, ci)
                }
                hk = k0; hidx = i0; hflag = 0;
                l1 = (((unsigned long long)k1) << 13) | i1;
                l2 = (((unsigned long long)k2) << 13) | i2;
                l3 = (((unsigned long long)k3) << 13) | i3;
                bound = l3 | 0x1000ull;
                hp = 1;
            }
            continue;                    // retry this round
        }
        if (lane == r - 1) nbr = m;      // rounds 1..20 record neighbors
        if (mine) {
            unsigned long long v = (hp == 1) ? l1 : (hp == 2) ? l2
                                 : (hp == 3) ? l3 : bound;
            hp++;
            hk    = (unsigned int)(v >> 13);
            hidx  = (unsigned int)v & 0xFFFu;
            hflag = (unsigned int)(v >> 12) & 1u;
        }
        r++;
    }

    // ---- softmax over the 20 neighbors (in-warp) --------------------------
    float e = -1e30f;
    if (lane < KSEL - 1) {
        float val = g_f1[row] + g_f2[browbase + (int)nbr];
        e = val > 0.f ? val : 0.2f * val;            // leaky relu 0.2
    }
    float mx = e;
#pragma unroll
    for (int off = 16; off; off >>= 1)
        mx = fmaxf(mx, __shfl_xor_sync(FULL, mx, off));
    float ex = (lane < KSEL - 1) ? expf(e - mx) : 0.f;
    float sm = ex;
#pragma unroll
    for (int off = 16; off; off >>= 1)
        sm += __shfl_xor_sync(FULL, sm, off);
    float attn = ex / sm;                            // valid on lanes < 20

    // ---- weighted Wh gather + base + elu (2 features per lane) ------------
    float acc0 = g_base[row * FDIM + lane];
    float acc1 = g_base[row * FDIM + 32 + lane];
#pragma unroll
    for (int j = 0; j < KSEL - 1; j++) {
        int   mj = (int)__shfl_sync(FULL, nbr, j);
        float aj = __shfl_sync(FULL, attn, j);
        const float* wr = g_Wh + (browbase + mj) * FDIM;
        acc0 = fmaf(aj, wr[lane],      acc0);
        acc1 = fmaf(aj, wr[32 + lane], acc1);
    }
    out[row * FDIM + lane]      = acc0 > 0.f ? acc0 : expm1f(acc0);
    out[row * FDIM + 32 + lane] = acc1 > 0.f ? acc1 : expm1f(acc1);
}

// ---------------- launch ----------------------------------------------------
extern "C" void kernel_launch(void* const* d_in, const int* in_sizes, int n_in,
                              void* d_out, int out_size) {
    (void)in_sizes; (void)n_in; (void)out_size;
    const float* x   = (const float*)d_in[0];
    const float* pos = (const float*)d_in[1];
    const float* W   = (const float*)d_in[2];
    const float* a   = (const float*)d_in[3];
    const float* Wp  = (const float*)d_in[4];
    const float* bp  = (const float*)d_in[5];
    float* out = (float*)d_out;

    prep_kernel<<<NB, FDIM>>>(x, pos, W, a, Wp, bp);
    knn_attn_kernel<<<NB / (TPB / 32), TPB>>>(out);
}